// round 10
// baseline (speedup 1.0000x reference)
#include <cuda_runtime.h>
#include <cuda_bf16.h>
#include <mma.h>
#include <cstdint>
#include <cstddef>

using namespace nvcuda;

// Problem constants (fixed by the dataset)
#define NP_ 100000
#define NQ_ 50000
#define D_  128
#define E_  600000

// ---------------------------------------------------------------------------
// Device scratch (static: no runtime allocation allowed)
// Feature matrices kept as bf16 hi/lo split pairs (hi+lo ~= fp32 to ~2^-17).
// ---------------------------------------------------------------------------
__device__ __align__(16) __nv_bfloat16 g_xPhi[(size_t)NP_ * D_];
__device__ __align__(16) __nv_bfloat16 g_xPlo[(size_t)NP_ * D_];
__device__ __align__(16) __nv_bfloat16 g_xQhi[(size_t)NQ_ * D_];
__device__ __align__(16) __nv_bfloat16 g_xQlo[(size_t)NQ_ * D_];
__device__ __align__(16) __nv_bfloat16 g_accPhi[(size_t)NP_ * D_];
__device__ __align__(16) __nv_bfloat16 g_accPlo[(size_t)NP_ * D_];
__device__ __align__(16) __nv_bfloat16 g_accQhi[(size_t)NQ_ * D_];
__device__ __align__(16) __nv_bfloat16 g_accQlo[(size_t)NQ_ * D_];
__device__ __align__(16) __nv_bfloat16 g_hPhi[(size_t)NP_ * D_];
__device__ __align__(16) __nv_bfloat16 g_hPlo[(size_t)NP_ * D_];
__device__ __align__(16) __nv_bfloat16 g_hQhi[(size_t)NQ_ * D_];
__device__ __align__(16) __nv_bfloat16 g_hQlo[(size_t)NQ_ * D_];
// Transposed weights WT[n][k] = W[k][n] (col-major KxN for wmma matrix_b),
// split hi/lo, indexed [Wl_pv0, Wr_pv0, Wl_vp0, Wr_vp0, Wl_pv1, Wr_pv1, Wl_vp1, Wr_vp1]
__device__ __align__(16) __nv_bfloat16 g_WThi[8][D_ * D_];
__device__ __align__(16) __nv_bfloat16 g_WTlo[8][D_ * D_];

// CSR (built once per launch; topology shared by both layers)
__device__ int g_degQ[NQ_];
__device__ int g_degP[NP_];
__device__ int g_offQ[NQ_ + 1];
__device__ int g_offP[NP_ + 1];
__device__ int g_curQ[NQ_];
__device__ int g_curP[NP_];
__device__ int g_csrQ[E_];
__device__ int g_csrP[E_];

__device__ __forceinline__ void bf16_split(float f, __nv_bfloat16& h, __nv_bfloat16& l) {
    h = __float2bfloat16(f);
    l = __float2bfloat16(f - __bfloat162float(h));
}

// ---------------------------------------------------------------------------
// Prep: split input features x into bf16 hi/lo arrays
// ---------------------------------------------------------------------------
__global__ void split_x_kernel(const float* __restrict__ xp,
                               const float* __restrict__ xq)
{
    size_t i0 = (size_t)blockIdx.x * blockDim.x + threadIdx.x;
    size_t stride = (size_t)gridDim.x * blockDim.x;
    const size_t nP4 = (size_t)NP_ * (D_ / 4);
    const size_t nQ4 = (size_t)NQ_ * (D_ / 4);
    for (size_t q = i0; q < nP4 + nQ4; q += stride) {
        const float* src;
        __nv_bfloat16 *dh, *dl;
        size_t off;
        if (q < nP4) { src = xp; dh = g_xPhi; dl = g_xPlo; off = q; }
        else         { src = xq; dh = g_xQhi; dl = g_xQlo; off = q - nP4; }
        float4 v = *reinterpret_cast<const float4*>(src + off * 4);
        __nv_bfloat162 h0 = __floats2bfloat162_rn(v.x, v.y);
        __nv_bfloat162 h1 = __floats2bfloat162_rn(v.z, v.w);
        float2 f0 = __bfloat1622float2(h0);
        float2 f1 = __bfloat1622float2(h1);
        __nv_bfloat162 l0 = __floats2bfloat162_rn(v.x - f0.x, v.y - f0.y);
        __nv_bfloat162 l1 = __floats2bfloat162_rn(v.z - f1.x, v.w - f1.y);
        uint2 uh = make_uint2(*reinterpret_cast<uint32_t*>(&h0),
                              *reinterpret_cast<uint32_t*>(&h1));
        uint2 ul = make_uint2(*reinterpret_cast<uint32_t*>(&l0),
                              *reinterpret_cast<uint32_t*>(&l1));
        *reinterpret_cast<uint2*>(dh + off * 4) = uh;
        *reinterpret_cast<uint2*>(dl + off * 4) = ul;
    }
}

// ---------------------------------------------------------------------------
// Prep: transpose + split the 8 weight matrices (W[k][n] -> WT[n][k] hi/lo)
// ---------------------------------------------------------------------------
__global__ void split_w_kernel(const float* w0, const float* w1,
                               const float* w2, const float* w3,
                               const float* w4, const float* w5,
                               const float* w6, const float* w7)
{
    const float* W[8] = {w0, w1, w2, w3, w4, w5, w6, w7};
    int i = blockIdx.x * blockDim.x + threadIdx.x;
    if (i >= 8 * D_ * D_) return;
    int mat = i >> 14;
    int idx = i & 16383;
    int n = idx >> 7;
    int k = idx & 127;
    float w = __ldg(W[mat] + k * D_ + n);
    __nv_bfloat16 h, l;
    bf16_split(w, h, l);
    g_WThi[mat][n * D_ + k] = h;
    g_WTlo[mat][n * D_ + k] = l;
}

// ---------------------------------------------------------------------------
// CSR build
// ---------------------------------------------------------------------------
__global__ void zero_deg_kernel() {
    int i = blockIdx.x * blockDim.x + threadIdx.x;
    int stride = gridDim.x * blockDim.x;
    for (int k = i; k < NQ_; k += stride) g_degQ[k] = 0;
    for (int k = i; k < NP_; k += stride) g_degP[k] = 0;
}

__global__ __launch_bounds__(256) void degree_kernel(
    const int* __restrict__ dst_pv, const int* __restrict__ dst_vp, int nE)
{
    int i = blockIdx.x * blockDim.x + threadIdx.x;
    if (i < nE)          atomicAdd(&g_degQ[__ldg(dst_pv + i)], 1);
    else if (i < 2 * nE) atomicAdd(&g_degP[__ldg(dst_vp + i - nE)], 1);
}

__global__ __launch_bounds__(1024) void scan_kernel() {
    const bool qside = (blockIdx.x == 0);
    const int n = qside ? NQ_ : NP_;
    int* deg = qside ? g_degQ : g_degP;
    int* off = qside ? g_offQ : g_offP;
    int* cur = qside ? g_curQ : g_curP;

    const int T = 1024;
    const int t = threadIdx.x;
    const int chunk = (n + T - 1) / T;
    const int lo = t * chunk;
    const int hi = (lo + chunk < n) ? lo + chunk : n;

    int s = 0;
    for (int i = lo; i < hi; ++i) s += deg[i];

    __shared__ int ps[1024];
    ps[t] = s;
    __syncthreads();
    for (int d = 1; d < T; d <<= 1) {
        int v = 0;
        if (t >= d) v = ps[t - d];
        __syncthreads();
        if (t >= d) ps[t] += v;
        __syncthreads();
    }
    int run = (t == 0) ? 0 : ps[t - 1];
    for (int i = lo; i < hi; ++i) {
        off[i] = run;
        cur[i] = run;
        run += deg[i];
    }
    if (t == 0) off[n] = ps[T - 1];
}

__global__ __launch_bounds__(256) void fill_kernel(
    const int* __restrict__ src_pv, const int* __restrict__ dst_pv,
    const int* __restrict__ src_vp, const int* __restrict__ dst_vp, int nE)
{
    int i = blockIdx.x * blockDim.x + threadIdx.x;
    if (i < nE) {
        int pos = atomicAdd(&g_curQ[__ldg(dst_pv + i)], 1);
        g_csrQ[pos] = __ldg(src_pv + i);
    } else if (i < 2 * nE) {
        int e = i - nE;
        int pos = atomicAdd(&g_curP[__ldg(dst_vp + e)], 1);
        g_csrP[pos] = __ldg(src_vp + e);
    }
}

// ---------------------------------------------------------------------------
// Gather-mean aggregation: one warp per destination node; writes hi/lo bf16.
//   SRC_H=false: gather fp32 x rows.  SRC_H=true: gather h hi/lo bf16 rows.
// ---------------------------------------------------------------------------
template <bool SRC_H>
__global__ __launch_bounds__(256) void agg_kernel(
    const float* __restrict__ x_p_in, const float* __restrict__ x_q_in)
{
    int gwarp = (int)((blockIdx.x * blockDim.x + threadIdx.x) >> 5);
    int lane = threadIdx.x & 31;
    if (gwarp >= NQ_ + NP_) return;

    const float* xf;
    const __nv_bfloat16 *xh, *xl;
    const int *off, *csr;
    __nv_bfloat16 *outh, *outl;
    int node;
    if (gwarp < NQ_) {
        node = gwarp;
        xf = x_p_in; xh = g_hPhi; xl = g_hPlo;
        off = g_offQ; csr = g_csrQ; outh = g_accQhi; outl = g_accQlo;
    } else {
        node = gwarp - NQ_;
        xf = x_q_in; xh = g_hQhi; xl = g_hQlo;
        off = g_offP; csr = g_csrP; outh = g_accPhi; outl = g_accPlo;
    }

    int beg = __ldg(off + node);
    int end = __ldg(off + node + 1);

    float4 s = make_float4(0.f, 0.f, 0.f, 0.f);
    if (!SRC_H) {
        int j = beg;
        for (; j + 2 <= end; j += 2) {
            int i0 = __ldg(csr + j);
            int i1 = __ldg(csr + j + 1);
            float4 v0 = *reinterpret_cast<const float4*>(xf + (size_t)i0 * D_ + lane * 4);
            float4 v1 = *reinterpret_cast<const float4*>(xf + (size_t)i1 * D_ + lane * 4);
            s.x += v0.x + v1.x; s.y += v0.y + v1.y;
            s.z += v0.z + v1.z; s.w += v0.w + v1.w;
        }
        for (; j < end; ++j) {
            int i0 = __ldg(csr + j);
            float4 v0 = *reinterpret_cast<const float4*>(xf + (size_t)i0 * D_ + lane * 4);
            s.x += v0.x; s.y += v0.y; s.z += v0.z; s.w += v0.w;
        }
    } else {
        for (int j = beg; j < end; ++j) {
            int i0 = __ldg(csr + j);
            uint2 uh = *reinterpret_cast<const uint2*>(xh + (size_t)i0 * D_ + lane * 4);
            uint2 ul = *reinterpret_cast<const uint2*>(xl + (size_t)i0 * D_ + lane * 4);
            float2 h0 = __bfloat1622float2(*reinterpret_cast<__nv_bfloat162*>(&uh.x));
            float2 h1 = __bfloat1622float2(*reinterpret_cast<__nv_bfloat162*>(&uh.y));
            float2 l0 = __bfloat1622float2(*reinterpret_cast<__nv_bfloat162*>(&ul.x));
            float2 l1 = __bfloat1622float2(*reinterpret_cast<__nv_bfloat162*>(&ul.y));
            s.x += h0.x + l0.x; s.y += h0.y + l0.y;
            s.z += h1.x + l1.x; s.w += h1.y + l1.y;
        }
    }

    int deg = end - beg;
    float r = 1.f / (float)(deg > 0 ? deg : 1);
    s.x *= r; s.y *= r; s.z *= r; s.w *= r;

    __nv_bfloat162 h0 = __floats2bfloat162_rn(s.x, s.y);
    __nv_bfloat162 h1 = __floats2bfloat162_rn(s.z, s.w);
    float2 f0 = __bfloat1622float2(h0);
    float2 f1 = __bfloat1622float2(h1);
    __nv_bfloat162 l0 = __floats2bfloat162_rn(s.x - f0.x, s.y - f0.y);
    __nv_bfloat162 l1 = __floats2bfloat162_rn(s.z - f1.x, s.w - f1.y);
    uint2 uh = make_uint2(*reinterpret_cast<uint32_t*>(&h0),
                          *reinterpret_cast<uint32_t*>(&h1));
    uint2 ul = make_uint2(*reinterpret_cast<uint32_t*>(&l0),
                          *reinterpret_cast<uint32_t*>(&l1));
    *reinterpret_cast<uint2*>(outh + (size_t)node * D_ + lane * 4) = uh;
    *reinterpret_cast<uint2*>(outl + (size_t)node * D_ + lane * 4) = ul;
}

// ---------------------------------------------------------------------------
// WMMA bf16-split GEMM (legacy tensor path, valid on plain sm_100):
//   D = acc@Wl + self@Wr  via 6 bf16 passes:
//     acc_hi@Wl_hi + acc_hi@Wl_lo + acc_lo@Wl_hi
//   + self_hi@Wr_hi + self_hi@Wr_lo + self_lo@Wr_hi
// CTA tile 128x128, 8 warps in 2x4 grid (64x32 each = 4x2 wmma 16x16x16
// fragments, fp32 accum kept across all passes). Per pass, A (128x128 bf16)
// and B (WT, col-major KxN) are staged into smem with ld=136 (272B row
// stride -> ldmatrix rows land in distinct bank groups, conflict-free).
// Epilogue: fragments -> smem float union -> bias [+ReLU+hi/lo split] or
// fp32 store.
// ---------------------------------------------------------------------------
#define LDAB 136
#define LDC  132
#define GEMM_SMEM (2 * 128 * LDAB * 2)   // A + B bf16 = 69632 bytes

template <bool LAYER1>
__global__ __launch_bounds__(256, 2) void wmma_gemm_kernel(
    const float* __restrict__ bias_q, const float* __restrict__ bias_p,
    float* __restrict__ out_q, float* __restrict__ out_p, int nQb)
{
    extern __shared__ char sm[];
    __nv_bfloat16 (*A_s)[LDAB] = reinterpret_cast<__nv_bfloat16(*)[LDAB]>(sm);
    __nv_bfloat16 (*B_s)[LDAB] =
        reinterpret_cast<__nv_bfloat16(*)[LDAB]>(sm + 128 * LDAB * 2);
    float (*C_s)[LDC] = reinterpret_cast<float(*)[LDC]>(sm);  // epilogue union

    const int tid = threadIdx.x;
    const int wid = tid >> 5;
    const bool qside = (int)blockIdx.x < nQb;
    const int blk = qside ? (int)blockIdx.x : (int)blockIdx.x - nQb;
    const int nrows = qside ? NQ_ : NP_;
    const int row0 = blk * 128;

    const __nv_bfloat16 *acchi, *acclo, *selfhi, *selflo;
    if (qside) {
        acchi = g_accQhi; acclo = g_accQlo;
        selfhi = LAYER1 ? g_hQhi : g_xQhi;
        selflo = LAYER1 ? g_hQlo : g_xQlo;
    } else {
        acchi = g_accPhi; acclo = g_accPlo;
        selfhi = LAYER1 ? g_hPhi : g_xPhi;
        selflo = LAYER1 ? g_hPlo : g_xPlo;
    }
    const int wl = (LAYER1 ? 4 : 0) + (qside ? 0 : 2);
    const int wr = wl + 1;
    const __nv_bfloat16* APASS[6] = {acchi, acchi, acclo, selfhi, selfhi, selflo};
    const __nv_bfloat16* BPASS[6] = {g_WThi[wl], g_WTlo[wl], g_WThi[wl],
                                     g_WThi[wr], g_WTlo[wr], g_WThi[wr]};
    const float* bias = qside ? bias_q : bias_p;

    // staging mapping: thread t -> row t>>1, 128B half (t&1)
    const int sr = tid >> 1;
    const int sh = (tid & 1) * 64;           // element offset (64 bf16 = 128B)
    int garow = row0 + sr;
    if (garow >= nrows) garow = nrows - 1;   // clamp; dup rows never stored

    // warp tiling: 2 (m) x 4 (n)
    const int m0 = (wid & 1) * 64;
    const int n0 = (wid >> 1) * 32;

    wmma::fragment<wmma::accumulator, 16, 16, 16, float> c[4][2];
#pragma unroll
    for (int i = 0; i < 4; i++)
#pragma unroll
        for (int j = 0; j < 2; j++) wmma::fill_fragment(c[i][j], 0.f);

#pragma unroll 1
    for (int pass = 0; pass < 6; ++pass) {
        // ---- stage A (rows) and B (WT rows = n) ----
        {
            const uint4* ga = reinterpret_cast<const uint4*>(
                APASS[pass] + (size_t)garow * D_ + sh);
            const uint4* gb = reinterpret_cast<const uint4*>(
                BPASS[pass] + (size_t)sr * D_ + sh);
            uint4* da = reinterpret_cast<uint4*>(&A_s[sr][sh]);
            uint4* db = reinterpret_cast<uint4*>(&B_s[sr][sh]);
#pragma unroll
            for (int i = 0; i < 8; i++) { da[i] = ga[i]; db[i] = gb[i]; }
        }
        __syncthreads();

        // ---- compute: 8 k-steps of 16 ----
#pragma unroll
        for (int ks = 0; ks < 8; ++ks) {
            const int k0 = ks * 16;
            wmma::fragment<wmma::matrix_a, 16, 16, 16, __nv_bfloat16,
                           wmma::row_major> a[4];
            wmma::fragment<wmma::matrix_b, 16, 16, 16, __nv_bfloat16,
                           wmma::col_major> bfr[2];
#pragma unroll
            for (int i = 0; i < 4; i++)
                wmma::load_matrix_sync(a[i], &A_s[m0 + 16 * i][k0], LDAB);
#pragma unroll
            for (int j = 0; j < 2; j++)
                wmma::load_matrix_sync(bfr[j], &B_s[n0 + 16 * j][k0], LDAB);
#pragma unroll
            for (int i = 0; i < 4; i++)
#pragma unroll
                for (int j = 0; j < 2; j++)
                    wmma::mma_sync(c[i][j], a[i], bfr[j], c[i][j]);
        }
        __syncthreads();
    }

    // ---- epilogue: fragments -> smem (union), then bias/ReLU/split/store ----
#pragma unroll
    for (int i = 0; i < 4; i++)
#pragma unroll
        for (int j = 0; j < 2; j++)
            wmma::store_matrix_sync(&C_s[m0 + 16 * i][n0 + 16 * j], c[i][j],
                                    LDC, wmma::mem_row_major);
    __syncthreads();

    const int er = tid >> 1;                 // output row 0..127
    const int ec = (tid & 1) * 64;           // column base 0 or 64
    const int orow = row0 + er;
    if (orow < nrows) {
        float* outp = qside ? out_q : out_p;
        __nv_bfloat16* hh = qside ? g_hQhi : g_hPhi;
        __nv_bfloat16* hl = qside ? g_hQlo : g_hPlo;
        if (LAYER1) {
            float* op = outp + (size_t)orow * D_ + ec;
#pragma unroll
            for (int cgrp = 0; cgrp < 64; cgrp += 4) {
                float4 v;
                v.x = C_s[er][ec + cgrp]     + __ldg(bias + ec + cgrp);
                v.y = C_s[er][ec + cgrp + 1] + __ldg(bias + ec + cgrp + 1);
                v.z = C_s[er][ec + cgrp + 2] + __ldg(bias + ec + cgrp + 2);
                v.w = C_s[er][ec + cgrp + 3] + __ldg(bias + ec + cgrp + 3);
                *reinterpret_cast<float4*>(op + cgrp) = v;
            }
        } else {
            __nv_bfloat16* ph = hh + (size_t)orow * D_ + ec;
            __nv_bfloat16* pl = hl + (size_t)orow * D_ + ec;
#pragma unroll
            for (int g = 0; g < 64; g += 8) {
                __nv_bfloat162 H[4], L[4];
#pragma unroll
                for (int j = 0; j < 4; j++) {
                    int cc = ec + g + j * 2;
                    float f0 = C_s[er][cc]     + __ldg(bias + cc);
                    float f1 = C_s[er][cc + 1] + __ldg(bias + cc + 1);
                    f0 = fmaxf(f0, 0.f);
                    f1 = fmaxf(f1, 0.f);
                    H[j] = __floats2bfloat162_rn(f0, f1);
                    float2 hf = __bfloat1622float2(H[j]);
                    L[j] = __floats2bfloat162_rn(f0 - hf.x, f1 - hf.y);
                }
                *reinterpret_cast<uint4*>(ph + g) = *reinterpret_cast<uint4*>(H);
                *reinterpret_cast<uint4*>(pl + g) = *reinterpret_cast<uint4*>(L);
            }
        }
    }
}

// ---------------------------------------------------------------------------
// kernel_launch — inputs classified by element count (see R4 notes)
// Output: [h_p (NP*D) | h_q (NQ*D)]
// ---------------------------------------------------------------------------
extern "C" void kernel_launch(void* const* d_in, const int* in_sizes, int n_in,
                              void* d_out, int out_size)
{
    (void)out_size;
    const float* x_p = nullptr;
    const float* x_q = nullptr;
    const float* W[8] = {nullptr};
    const float* b[4] = {nullptr};
    const int*   eidx[4] = {nullptr};
    int wi = 0, bi = 0, ei = 0;
    int E = E_;

    for (int i = 0; i < n_in; i++) {
        int n = in_sizes[i];
        if (n == NP_ * D_)            x_p = (const float*)d_in[i];
        else if (n == NQ_ * D_)       x_q = (const float*)d_in[i];
        else if (n == D_ * D_)        { if (wi < 8) W[wi++] = (const float*)d_in[i]; }
        else if (n == D_)             { if (bi < 4) b[bi++] = (const float*)d_in[i]; }
        else                          { if (ei < 4) { eidx[ei++] = (const int*)d_in[i]; E = n; } }
    }

    const int* src_pv = eidx[0];
    const int* dst_pv = eidx[1];
    const int* src_vp = eidx[2];
    const int* dst_vp = eidx[3];
    float* out = (float*)d_out;
    float* out_p = out;
    float* out_q = out + (size_t)NP_ * D_;

    int eblocks = (2 * E + 255) / 256;
    int ablocks = ((NQ_ + NP_) * 32 + 255) / 256;
    int nQb = (NQ_ + 127) / 128;     // 391
    int nPb = (NP_ + 127) / 128;     // 782
    dim3 gG(nQb + nPb);

    cudaFuncSetAttribute(wmma_gemm_kernel<false>,
                         cudaFuncAttributeMaxDynamicSharedMemorySize, GEMM_SMEM);
    cudaFuncSetAttribute(wmma_gemm_kernel<true>,
                         cudaFuncAttributeMaxDynamicSharedMemorySize, GEMM_SMEM);

    // ---- one-time preps ----
    split_w_kernel<<<512, 256>>>(W[0], W[1], W[2], W[3], W[4], W[5], W[6], W[7]);
    split_x_kernel<<<4096, 256>>>(x_p, x_q);
    zero_deg_kernel<<<256, 256>>>();
    degree_kernel<<<eblocks, 256>>>(dst_pv, dst_vp, E);
    scan_kernel<<<2, 1024>>>();
    fill_kernel<<<eblocks, 256>>>(src_pv, dst_pv, src_vp, dst_vp, E);

    // ---- Layer 0 ----
    agg_kernel<false><<<ablocks, 256>>>(x_p, x_q);
    wmma_gemm_kernel<false><<<gG, 256, GEMM_SMEM>>>(b[0], b[1], nullptr, nullptr, nQb);

    // ---- Layer 1 ----
    agg_kernel<true><<<ablocks, 256>>>(nullptr, nullptr);
    wmma_gemm_kernel<true><<<gG, 256, GEMM_SMEM>>>(b[2], b[3], out_q, out_p, nQb);
}

// round 11
// speedup vs baseline: 1.1715x; 1.1715x over previous
#include <cuda_runtime.h>
#include <cuda_bf16.h>
#include <mma.h>
#include <cstdint>
#include <cstddef>

using namespace nvcuda;

// Problem constants (fixed by the dataset)
#define NP_ 100000
#define NQ_ 50000
#define D_  128
#define E_  600000

// ---------------------------------------------------------------------------
// Device scratch (static: no runtime allocation allowed)
// Feature matrices kept as bf16 hi/lo split pairs (hi+lo ~= fp32 to ~2^-17).
// ---------------------------------------------------------------------------
__device__ __align__(16) __nv_bfloat16 g_xPhi[(size_t)NP_ * D_];
__device__ __align__(16) __nv_bfloat16 g_xPlo[(size_t)NP_ * D_];
__device__ __align__(16) __nv_bfloat16 g_xQhi[(size_t)NQ_ * D_];
__device__ __align__(16) __nv_bfloat16 g_xQlo[(size_t)NQ_ * D_];
__device__ __align__(16) __nv_bfloat16 g_accPhi[(size_t)NP_ * D_];
__device__ __align__(16) __nv_bfloat16 g_accPlo[(size_t)NP_ * D_];
__device__ __align__(16) __nv_bfloat16 g_accQhi[(size_t)NQ_ * D_];
__device__ __align__(16) __nv_bfloat16 g_accQlo[(size_t)NQ_ * D_];
__device__ __align__(16) __nv_bfloat16 g_hPhi[(size_t)NP_ * D_];
__device__ __align__(16) __nv_bfloat16 g_hPlo[(size_t)NP_ * D_];
__device__ __align__(16) __nv_bfloat16 g_hQhi[(size_t)NQ_ * D_];
__device__ __align__(16) __nv_bfloat16 g_hQlo[(size_t)NQ_ * D_];
// Transposed weights WT[n][k] = W[k][n] (col-major KxN for wmma matrix_b),
// split hi/lo, indexed [Wl_pv0, Wr_pv0, Wl_vp0, Wr_vp0, Wl_pv1, Wr_pv1, Wl_vp1, Wr_vp1]
__device__ __align__(16) __nv_bfloat16 g_WThi[8][D_ * D_];
__device__ __align__(16) __nv_bfloat16 g_WTlo[8][D_ * D_];

// CSR (built once per launch; topology shared by both layers)
__device__ int g_degQ[NQ_];
__device__ int g_degP[NP_];
__device__ int g_offQ[NQ_ + 1];
__device__ int g_offP[NP_ + 1];
__device__ int g_curQ[NQ_];
__device__ int g_curP[NP_];
__device__ int g_csrQ[E_];
__device__ int g_csrP[E_];

__device__ __forceinline__ void bf16_split(float f, __nv_bfloat16& h, __nv_bfloat16& l) {
    h = __float2bfloat16(f);
    l = __float2bfloat16(f - __bfloat162float(h));
}

__device__ __forceinline__ uint32_t smem_u32(const void* p) {
    uint32_t a;
    asm("{ .reg .u64 t; cvta.to.shared.u64 t, %1; cvt.u32.u64 %0, t; }"
        : "=r"(a) : "l"(p));
    return a;
}

#define CP_ASYNC16(dst, src) \
    asm volatile("cp.async.cg.shared.global [%0], [%1], 16;" \
                 :: "r"(dst), "l"(src) : "memory")
#define CP_COMMIT() asm volatile("cp.async.commit_group;" ::: "memory")
#define CP_WAIT1()  asm volatile("cp.async.wait_group 1;" ::: "memory")
#define CP_WAIT0()  asm volatile("cp.async.wait_group 0;" ::: "memory")

// ---------------------------------------------------------------------------
// Prep: split input features x into bf16 hi/lo arrays
// ---------------------------------------------------------------------------
__global__ void split_x_kernel(const float* __restrict__ xp,
                               const float* __restrict__ xq)
{
    size_t i0 = (size_t)blockIdx.x * blockDim.x + threadIdx.x;
    size_t stride = (size_t)gridDim.x * blockDim.x;
    const size_t nP4 = (size_t)NP_ * (D_ / 4);
    const size_t nQ4 = (size_t)NQ_ * (D_ / 4);
    for (size_t q = i0; q < nP4 + nQ4; q += stride) {
        const float* src;
        __nv_bfloat16 *dh, *dl;
        size_t off;
        if (q < nP4) { src = xp; dh = g_xPhi; dl = g_xPlo; off = q; }
        else         { src = xq; dh = g_xQhi; dl = g_xQlo; off = q - nP4; }
        float4 v = *reinterpret_cast<const float4*>(src + off * 4);
        __nv_bfloat162 h0 = __floats2bfloat162_rn(v.x, v.y);
        __nv_bfloat162 h1 = __floats2bfloat162_rn(v.z, v.w);
        float2 f0 = __bfloat1622float2(h0);
        float2 f1 = __bfloat1622float2(h1);
        __nv_bfloat162 l0 = __floats2bfloat162_rn(v.x - f0.x, v.y - f0.y);
        __nv_bfloat162 l1 = __floats2bfloat162_rn(v.z - f1.x, v.w - f1.y);
        uint2 uh = make_uint2(*reinterpret_cast<uint32_t*>(&h0),
                              *reinterpret_cast<uint32_t*>(&h1));
        uint2 ul = make_uint2(*reinterpret_cast<uint32_t*>(&l0),
                              *reinterpret_cast<uint32_t*>(&l1));
        *reinterpret_cast<uint2*>(dh + off * 4) = uh;
        *reinterpret_cast<uint2*>(dl + off * 4) = ul;
    }
}

// ---------------------------------------------------------------------------
// Prep: transpose + split the 8 weight matrices (W[k][n] -> WT[n][k] hi/lo)
// ---------------------------------------------------------------------------
__global__ void split_w_kernel(const float* w0, const float* w1,
                               const float* w2, const float* w3,
                               const float* w4, const float* w5,
                               const float* w6, const float* w7)
{
    const float* W[8] = {w0, w1, w2, w3, w4, w5, w6, w7};
    int i = blockIdx.x * blockDim.x + threadIdx.x;
    if (i >= 8 * D_ * D_) return;
    int mat = i >> 14;
    int idx = i & 16383;
    int n = idx >> 7;
    int k = idx & 127;
    float w = __ldg(W[mat] + k * D_ + n);
    __nv_bfloat16 h, l;
    bf16_split(w, h, l);
    g_WThi[mat][n * D_ + k] = h;
    g_WTlo[mat][n * D_ + k] = l;
}

// ---------------------------------------------------------------------------
// CSR build
// ---------------------------------------------------------------------------
__global__ void zero_deg_kernel() {
    int i = blockIdx.x * blockDim.x + threadIdx.x;
    int stride = gridDim.x * blockDim.x;
    for (int k = i; k < NQ_; k += stride) g_degQ[k] = 0;
    for (int k = i; k < NP_; k += stride) g_degP[k] = 0;
}

__global__ __launch_bounds__(256) void degree_kernel(
    const int* __restrict__ dst_pv, const int* __restrict__ dst_vp, int nE)
{
    int i = blockIdx.x * blockDim.x + threadIdx.x;
    if (i < nE)          atomicAdd(&g_degQ[__ldg(dst_pv + i)], 1);
    else if (i < 2 * nE) atomicAdd(&g_degP[__ldg(dst_vp + i - nE)], 1);
}

__global__ __launch_bounds__(1024) void scan_kernel() {
    const bool qside = (blockIdx.x == 0);
    const int n = qside ? NQ_ : NP_;
    int* deg = qside ? g_degQ : g_degP;
    int* off = qside ? g_offQ : g_offP;
    int* cur = qside ? g_curQ : g_curP;

    const int T = 1024;
    const int t = threadIdx.x;
    const int chunk = (n + T - 1) / T;
    const int lo = t * chunk;
    const int hi = (lo + chunk < n) ? lo + chunk : n;

    int s = 0;
    for (int i = lo; i < hi; ++i) s += deg[i];

    __shared__ int ps[1024];
    ps[t] = s;
    __syncthreads();
    for (int d = 1; d < T; d <<= 1) {
        int v = 0;
        if (t >= d) v = ps[t - d];
        __syncthreads();
        if (t >= d) ps[t] += v;
        __syncthreads();
    }
    int run = (t == 0) ? 0 : ps[t - 1];
    for (int i = lo; i < hi; ++i) {
        off[i] = run;
        cur[i] = run;
        run += deg[i];
    }
    if (t == 0) off[n] = ps[T - 1];
}

__global__ __launch_bounds__(256) void fill_kernel(
    const int* __restrict__ src_pv, const int* __restrict__ dst_pv,
    const int* __restrict__ src_vp, const int* __restrict__ dst_vp, int nE)
{
    int i = blockIdx.x * blockDim.x + threadIdx.x;
    if (i < nE) {
        int pos = atomicAdd(&g_curQ[__ldg(dst_pv + i)], 1);
        g_csrQ[pos] = __ldg(src_pv + i);
    } else if (i < 2 * nE) {
        int e = i - nE;
        int pos = atomicAdd(&g_curP[__ldg(dst_vp + e)], 1);
        g_csrP[pos] = __ldg(src_vp + e);
    }
}

// ---------------------------------------------------------------------------
// Gather-mean aggregation: one warp per destination node; writes hi/lo bf16.
// ---------------------------------------------------------------------------
template <bool SRC_H>
__global__ __launch_bounds__(256) void agg_kernel(
    const float* __restrict__ x_p_in, const float* __restrict__ x_q_in)
{
    int gwarp = (int)((blockIdx.x * blockDim.x + threadIdx.x) >> 5);
    int lane = threadIdx.x & 31;
    if (gwarp >= NQ_ + NP_) return;

    const float* xf;
    const __nv_bfloat16 *xh, *xl;
    const int *off, *csr;
    __nv_bfloat16 *outh, *outl;
    int node;
    if (gwarp < NQ_) {
        node = gwarp;
        xf = x_p_in; xh = g_hPhi; xl = g_hPlo;
        off = g_offQ; csr = g_csrQ; outh = g_accQhi; outl = g_accQlo;
    } else {
        node = gwarp - NQ_;
        xf = x_q_in; xh = g_hQhi; xl = g_hQlo;
        off = g_offP; csr = g_csrP; outh = g_accPhi; outl = g_accPlo;
    }

    int beg = __ldg(off + node);
    int end = __ldg(off + node + 1);

    float4 s = make_float4(0.f, 0.f, 0.f, 0.f);
    if (!SRC_H) {
        int j = beg;
        for (; j + 2 <= end; j += 2) {
            int i0 = __ldg(csr + j);
            int i1 = __ldg(csr + j + 1);
            float4 v0 = *reinterpret_cast<const float4*>(xf + (size_t)i0 * D_ + lane * 4);
            float4 v1 = *reinterpret_cast<const float4*>(xf + (size_t)i1 * D_ + lane * 4);
            s.x += v0.x + v1.x; s.y += v0.y + v1.y;
            s.z += v0.z + v1.z; s.w += v0.w + v1.w;
        }
        for (; j < end; ++j) {
            int i0 = __ldg(csr + j);
            float4 v0 = *reinterpret_cast<const float4*>(xf + (size_t)i0 * D_ + lane * 4);
            s.x += v0.x; s.y += v0.y; s.z += v0.z; s.w += v0.w;
        }
    } else {
        for (int j = beg; j < end; ++j) {
            int i0 = __ldg(csr + j);
            uint2 uh = *reinterpret_cast<const uint2*>(xh + (size_t)i0 * D_ + lane * 4);
            uint2 ul = *reinterpret_cast<const uint2*>(xl + (size_t)i0 * D_ + lane * 4);
            float2 h0 = __bfloat1622float2(*reinterpret_cast<__nv_bfloat162*>(&uh.x));
            float2 h1 = __bfloat1622float2(*reinterpret_cast<__nv_bfloat162*>(&uh.y));
            float2 l0 = __bfloat1622float2(*reinterpret_cast<__nv_bfloat162*>(&ul.x));
            float2 l1 = __bfloat1622float2(*reinterpret_cast<__nv_bfloat162*>(&ul.y));
            s.x += h0.x + l0.x; s.y += h0.y + l0.y;
            s.z += h1.x + l1.x; s.w += h1.y + l1.y;
        }
    }

    int deg = end - beg;
    float r = 1.f / (float)(deg > 0 ? deg : 1);
    s.x *= r; s.y *= r; s.z *= r; s.w *= r;

    __nv_bfloat162 h0 = __floats2bfloat162_rn(s.x, s.y);
    __nv_bfloat162 h1 = __floats2bfloat162_rn(s.z, s.w);
    float2 f0 = __bfloat1622float2(h0);
    float2 f1 = __bfloat1622float2(h1);
    __nv_bfloat162 l0 = __floats2bfloat162_rn(s.x - f0.x, s.y - f0.y);
    __nv_bfloat162 l1 = __floats2bfloat162_rn(s.z - f1.x, s.w - f1.y);
    uint2 uh = make_uint2(*reinterpret_cast<uint32_t*>(&h0),
                          *reinterpret_cast<uint32_t*>(&h1));
    uint2 ul = make_uint2(*reinterpret_cast<uint32_t*>(&l0),
                          *reinterpret_cast<uint32_t*>(&l1));
    *reinterpret_cast<uint2*>(outh + (size_t)node * D_ + lane * 4) = uh;
    *reinterpret_cast<uint2*>(outl + (size_t)node * D_ + lane * 4) = ul;
}

// ---------------------------------------------------------------------------
// WMMA bf16-split GEMM with cp.async double-buffered pipeline.
//   D = acc@Wl + self@Wr as a unified K=768 loop: 12 chunks of K=64,
//   A chunks [acchi,acchi,acclo,selfhi,selfhi,selflo] (each used at its
//   k-half), B chunks [Wlhi,Wllo,Wlhi,Wrhi,Wrlo,Wrhi].
// CTA tile 128x128, 8 warps (2m x 4n, 64x32 each = 4x2 wmma frags, fp32
// accum persists across all chunks). Chunk staging via cp.async.cg 16B,
// 2-deep (wait_group 1): chunk i+2's loads run under chunk i's MMAs.
// ld = 72 elements (144B) -> ldmatrix phases conflict-free.
// ---------------------------------------------------------------------------
#define LDS_PAD 72
#define CHUNK_BYTES (128 * LDS_PAD * 2)          // 18432
#define LDC  132
#define GEMM_SMEM (4 * CHUNK_BYTES)              // A0,A1,B0,B1 = 73728

template <bool LAYER1>
__global__ __launch_bounds__(256, 2) void wmma_gemm_kernel(
    const float* __restrict__ bias_q, const float* __restrict__ bias_p,
    float* __restrict__ out_q, float* __restrict__ out_p, int nQb)
{
    extern __shared__ char sm[];
    float (*C_s)[LDC] = reinterpret_cast<float(*)[LDC]>(sm);  // epilogue union

    const int tid = threadIdx.x;
    const int wid = tid >> 5;
    const bool qside = (int)blockIdx.x < nQb;
    const int blk = qside ? (int)blockIdx.x : (int)blockIdx.x - nQb;
    const int nrows = qside ? NQ_ : NP_;
    const int row0 = blk * 128;

    const __nv_bfloat16 *acchi, *acclo, *selfhi, *selflo;
    if (qside) {
        acchi = g_accQhi; acclo = g_accQlo;
        selfhi = LAYER1 ? g_hQhi : g_xQhi;
        selflo = LAYER1 ? g_hQlo : g_xQlo;
    } else {
        acchi = g_accPhi; acclo = g_accPlo;
        selfhi = LAYER1 ? g_hPhi : g_xPhi;
        selflo = LAYER1 ? g_hPlo : g_xPlo;
    }
    const int wl = (LAYER1 ? 4 : 0) + (qside ? 0 : 2);
    const int wr = wl + 1;
    const __nv_bfloat16* APASS[6] = {acchi, acchi, acclo, selfhi, selfhi, selflo};
    const __nv_bfloat16* BPASS[6] = {g_WThi[wl], g_WTlo[wl], g_WThi[wl],
                                     g_WThi[wr], g_WTlo[wr], g_WThi[wr]};
    const float* bias = qside ? bias_q : bias_p;

    // staging mapping: thread t -> row t>>1, 64B half (t&1)
    const int sr = tid >> 1;                 // row / WT-row 0..127
    const int sh2 = (tid & 1) * 32;          // element offset 0 or 32
    int garow = row0 + sr;
    if (garow >= nrows) garow = nrows - 1;   // clamp; dup rows never stored

    const uint32_t smA[2] = {smem_u32(sm), smem_u32(sm + CHUNK_BYTES)};
    const uint32_t smB[2] = {smem_u32(sm + 2 * CHUNK_BYTES),
                             smem_u32(sm + 3 * CHUNK_BYTES)};

    auto stage = [&](int c, int buf) {
        const int pass = c >> 1;
        const int kc = (c & 1) * 64;
        const char* ga = (const char*)(APASS[pass] + (size_t)garow * D_ + kc + sh2);
        const char* gb = (const char*)(BPASS[pass] + (size_t)sr * D_ + kc + sh2);
        const uint32_t sa = smA[buf] + (uint32_t)(sr * LDS_PAD + sh2) * 2;
        const uint32_t sb = smB[buf] + (uint32_t)(sr * LDS_PAD + sh2) * 2;
#pragma unroll
        for (int i = 0; i < 4; i++) {
            CP_ASYNC16(sa + i * 16, ga + i * 16);
            CP_ASYNC16(sb + i * 16, gb + i * 16);
        }
        CP_COMMIT();
    };

    // warp tiling: 2 (m) x 4 (n)
    const int m0 = (wid & 1) * 64;
    const int n0 = (wid >> 1) * 32;

    wmma::fragment<wmma::accumulator, 16, 16, 16, float> c[4][2];
#pragma unroll
    for (int i = 0; i < 4; i++)
#pragma unroll
        for (int j = 0; j < 2; j++) wmma::fill_fragment(c[i][j], 0.f);

    stage(0, 0);
    stage(1, 1);

#pragma unroll 1
    for (int cidx = 0; cidx < 12; ++cidx) {
        const int buf = cidx & 1;
        if (cidx < 11) CP_WAIT1(); else CP_WAIT0();
        __syncthreads();

        const __nv_bfloat16* As =
            reinterpret_cast<const __nv_bfloat16*>(sm + buf * CHUNK_BYTES);
        const __nv_bfloat16* Bs =
            reinterpret_cast<const __nv_bfloat16*>(sm + (2 + buf) * CHUNK_BYTES);
#pragma unroll
        for (int ks = 0; ks < 4; ++ks) {
            const int k0 = ks * 16;
            wmma::fragment<wmma::matrix_b, 16, 16, 16, __nv_bfloat16,
                           wmma::col_major> bfr[2];
#pragma unroll
            for (int j = 0; j < 2; j++)
                wmma::load_matrix_sync(bfr[j], Bs + (n0 + 16 * j) * LDS_PAD + k0,
                                       LDS_PAD);
#pragma unroll
            for (int i = 0; i < 4; i++) {
                wmma::fragment<wmma::matrix_a, 16, 16, 16, __nv_bfloat16,
                               wmma::row_major> a;
                wmma::load_matrix_sync(a, As + (m0 + 16 * i) * LDS_PAD + k0,
                                       LDS_PAD);
                wmma::mma_sync(c[i][0], a, bfr[0], c[i][0]);
                wmma::mma_sync(c[i][1], a, bfr[1], c[i][1]);
            }
        }
        __syncthreads();                     // all warps done with buf
        if (cidx + 2 < 12) stage(cidx + 2, buf);
    }

    // ---- epilogue: fragments -> smem (union), then bias/ReLU/split/store ----
#pragma unroll
    for (int i = 0; i < 4; i++)
#pragma unroll
        for (int j = 0; j < 2; j++)
            wmma::store_matrix_sync(&C_s[m0 + 16 * i][n0 + 16 * j], c[i][j],
                                    LDC, wmma::mem_row_major);
    __syncthreads();

    const int er = tid >> 1;                 // output row 0..127
    const int ec = (tid & 1) * 64;           // column base 0 or 64
    const int orow = row0 + er;
    if (orow < nrows) {
        float* outp = qside ? out_q : out_p;
        __nv_bfloat16* hh = qside ? g_hQhi : g_hPhi;
        __nv_bfloat16* hl = qside ? g_hQlo : g_hPlo;
        if (LAYER1) {
            float* op = outp + (size_t)orow * D_ + ec;
#pragma unroll
            for (int cgrp = 0; cgrp < 64; cgrp += 4) {
                float4 v;
                v.x = C_s[er][ec + cgrp]     + __ldg(bias + ec + cgrp);
                v.y = C_s[er][ec + cgrp + 1] + __ldg(bias + ec + cgrp + 1);
                v.z = C_s[er][ec + cgrp + 2] + __ldg(bias + ec + cgrp + 2);
                v.w = C_s[er][ec + cgrp + 3] + __ldg(bias + ec + cgrp + 3);
                *reinterpret_cast<float4*>(op + cgrp) = v;
            }
        } else {
            __nv_bfloat16* ph = hh + (size_t)orow * D_ + ec;
            __nv_bfloat16* pl = hl + (size_t)orow * D_ + ec;
#pragma unroll
            for (int g = 0; g < 64; g += 8) {
                __nv_bfloat162 H[4], L[4];
#pragma unroll
                for (int j = 0; j < 4; j++) {
                    int cc = ec + g + j * 2;
                    float f0 = C_s[er][cc]     + __ldg(bias + cc);
                    float f1 = C_s[er][cc + 1] + __ldg(bias + cc + 1);
                    f0 = fmaxf(f0, 0.f);
                    f1 = fmaxf(f1, 0.f);
                    H[j] = __floats2bfloat162_rn(f0, f1);
                    float2 hf = __bfloat1622float2(H[j]);
                    L[j] = __floats2bfloat162_rn(f0 - hf.x, f1 - hf.y);
                }
                *reinterpret_cast<uint4*>(ph + g) = *reinterpret_cast<uint4*>(H);
                *reinterpret_cast<uint4*>(pl + g) = *reinterpret_cast<uint4*>(L);
            }
        }
    }
}

// ---------------------------------------------------------------------------
// kernel_launch — inputs classified by element count (see R4 notes)
// Output: [h_p (NP*D) | h_q (NQ*D)]
// ---------------------------------------------------------------------------
extern "C" void kernel_launch(void* const* d_in, const int* in_sizes, int n_in,
                              void* d_out, int out_size)
{
    (void)out_size;
    const float* x_p = nullptr;
    const float* x_q = nullptr;
    const float* W[8] = {nullptr};
    const float* b[4] = {nullptr};
    const int*   eidx[4] = {nullptr};
    int wi = 0, bi = 0, ei = 0;
    int E = E_;

    for (int i = 0; i < n_in; i++) {
        int n = in_sizes[i];
        if (n == NP_ * D_)            x_p = (const float*)d_in[i];
        else if (n == NQ_ * D_)       x_q = (const float*)d_in[i];
        else if (n == D_ * D_)        { if (wi < 8) W[wi++] = (const float*)d_in[i]; }
        else if (n == D_)             { if (bi < 4) b[bi++] = (const float*)d_in[i]; }
        else                          { if (ei < 4) { eidx[ei++] = (const int*)d_in[i]; E = n; } }
    }

    const int* src_pv = eidx[0];
    const int* dst_pv = eidx[1];
    const int* src_vp = eidx[2];
    const int* dst_vp = eidx[3];
    float* out = (float*)d_out;
    float* out_p = out;
    float* out_q = out + (size_t)NP_ * D_;

    int eblocks = (2 * E + 255) / 256;
    int ablocks = ((NQ_ + NP_) * 32 + 255) / 256;
    int nQb = (NQ_ + 127) / 128;     // 391
    int nPb = (NP_ + 127) / 128;     // 782
    dim3 gG(nQb + nPb);

    cudaFuncSetAttribute(wmma_gemm_kernel<false>,
                         cudaFuncAttributeMaxDynamicSharedMemorySize, GEMM_SMEM);
    cudaFuncSetAttribute(wmma_gemm_kernel<true>,
                         cudaFuncAttributeMaxDynamicSharedMemorySize, GEMM_SMEM);

    // ---- one-time preps ----
    split_w_kernel<<<512, 256>>>(W[0], W[1], W[2], W[3], W[4], W[5], W[6], W[7]);
    split_x_kernel<<<4096, 256>>>(x_p, x_q);
    zero_deg_kernel<<<256, 256>>>();
    degree_kernel<<<eblocks, 256>>>(dst_pv, dst_vp, E);
    scan_kernel<<<2, 1024>>>();
    fill_kernel<<<eblocks, 256>>>(src_pv, dst_pv, src_vp, dst_vp, E);

    // ---- Layer 0 ----
    agg_kernel<false><<<ablocks, 256>>>(x_p, x_q);
    wmma_gemm_kernel<false><<<gG, 256, GEMM_SMEM>>>(b[0], b[1], nullptr, nullptr, nQb);

    // ---- Layer 1 ----
    agg_kernel<true><<<ablocks, 256>>>(nullptr, nullptr);
    wmma_gemm_kernel<true><<<gG, 256, GEMM_SMEM>>>(b[2], b[3], out_q, out_p, nQb);
}